// round 16
// baseline (speedup 1.0000x reference)
#include <cuda_runtime.h>
#include <cstdint>

// ---------------------------------------------------------------------------
// P2G quadratic B-spline scatter, 64^3 grid, B<=8 batches.
//
//  - float2 scratch grid (w, w*prob), z-padded rows (68 cells, slot=z+2) so
//    the 3 z-taps always fit two aligned 16B windows -> 18 red.v4 lanes per
//    particle (measured chip atomic-throughput floor ~1.29 cyc/lane).
//  - no zero kernel: __device__ globals load zeroed; finalize re-zeros the
//    interior slots it reads. Pad slots are never read, so they are allowed
//    to accumulate (cannot affect output; deterministic per call).
// ---------------------------------------------------------------------------

#define GRID_N   64
#define GRID_N3  (GRID_N * GRID_N * GRID_N)
#define B_MAX    8
#define ROWLEN   68                          // 64 + 2 pad each side
#define NROWS    (B_MAX * GRID_N * GRID_N)   // 32768
#define NCELL_SCRATCH (NROWS * ROWLEN)

__device__ float2 g_acc[NCELL_SCRATCH];      // zero-initialized at load

// ---------------------------------------------------------------------------

__device__ __forceinline__ void red_add_v4(float2* addr,
                                           float a, float b, float c, float d) {
    asm volatile("red.global.add.v4.f32 [%0], {%1, %2, %3, %4};"
                 :: "l"(addr), "f"(a), "f"(b), "f"(c), "f"(d)
                 : "memory");
}

__global__ void __launch_bounds__(256)
p2g_scatter_kernel(const float* __restrict__ pos,
                   const float* __restrict__ prob,
                   const int*   __restrict__ bidx,
                   int L) {
    int i = blockIdx.x * blockDim.x + threadIdx.x;
    if (i >= L) return;

    const float EPS_CLIP = 1e-5f;
    const float HI       = 1.0f - 1e-5f;

    float px = fminf(fmaxf(pos[3 * i + 0], EPS_CLIP), HI);
    float py = fminf(fmaxf(pos[3 * i + 1], EPS_CLIP), HI);
    float pz = fminf(fmaxf(pos[3 * i + 2], EPS_CLIP), HI);

    float Xx = px * 64.0f;
    float Xy = py * 64.0f;
    float Xz = pz * 64.0f;

    int bx = (int)Xx;
    int by = (int)Xy;
    int bz = (int)Xz;

    float fx = Xx - (float)bx;
    float fy = Xy - (float)by;
    float fz = Xz - (float)bz;

    float wx[3], wy[3], wz0, wz1, wz2;
    wx[0] = 0.5f * (1.0f - fx) * (1.0f - fx);
    wx[1] = 0.75f - (fx - 0.5f) * (fx - 0.5f);
    wx[2] = 0.5f * fx * fx;
    wy[0] = 0.5f * (1.0f - fy) * (1.0f - fy);
    wy[1] = 0.75f - (fy - 0.5f) * (fy - 0.5f);
    wy[2] = 0.5f * fy * fy;
    wz0 = 0.5f * (1.0f - fz) * (1.0f - fz);
    wz1 = 0.75f - (fz - 0.5f) * (fz - 0.5f);
    wz2 = 0.5f * fz * fz;

    float p_val = prob[i];
    int   brow  = bidx[i] * (GRID_N * GRID_N);

    // shift 3 z-taps (slots bz+1..bz+3) into an aligned 4-cell window
    int zb    = bz + 1;          // in [1, 64]
    int shift = zb & 1;
    int a     = zb - shift;      // even, in [0, 64]; a+3 <= 67

    float z0 = shift ? 0.0f : wz0;
    float z1 = shift ? wz0  : wz1;
    float z2 = shift ? wz1  : wz2;
    float z3 = shift ? wz2  : 0.0f;
    float q0 = z0 * p_val;
    float q1 = z1 * p_val;
    float q2 = z2 * p_val;
    float q3 = z3 * p_val;

    #pragma unroll
    for (int ox = 0; ox < 3; ox++) {
        int tx = bx - 1 + ox;
        if ((unsigned)tx >= (unsigned)GRID_N) continue;
        int xrow = brow + tx * GRID_N;
        #pragma unroll
        for (int oy = 0; oy < 3; oy++) {
            int ty = by - 1 + oy;
            if ((unsigned)ty >= (unsigned)GRID_N) continue;
            float c = wx[ox] * wy[oy];
            float2* base = g_acc + (size_t)(xrow + ty) * ROWLEN + a;
            red_add_v4(base,     c * z0, c * q0, c * z1, c * q1);
            red_add_v4(base + 2, c * z2, c * q2, c * z3, c * q3);
        }
    }
}

// ---------------------------------------------------------------------------
// Finalize + reset: one thread per 8 output cells (two float4 out stores).
// Reads 4 independent float4 scratch words (MLP=4), writes the divide
// results, zeros the interior slots it read. Pad slots are never touched.

__global__ void __launch_bounds__(256)
p2g_finalize_kernel(float* __restrict__ out, int nocts) {
    int t = blockIdx.x * blockDim.x + threadIdx.x;
    if (t >= nocts) return;                  // nocts = B * 4096 * 8

    int row = t >> 3;                        // (b*64 + x)*64 + y
    int zo  = (t & 7) << 3;                  // 0,8,...,56

    float2* rp = g_acc + (size_t)row * ROWLEN + zo + 2;

    float4 c0 = *reinterpret_cast<float4*>(rp + 0);   // (w0,p0,w1,p1)
    float4 c1 = *reinterpret_cast<float4*>(rp + 2);
    float4 c2 = *reinterpret_cast<float4*>(rp + 4);
    float4 c3 = *reinterpret_cast<float4*>(rp + 6);

    float4 o0, o1;
    o0.x = c0.y / (c0.x + 1e-7f);
    o0.y = c0.w / (c0.z + 1e-7f);
    o0.z = c1.y / (c1.x + 1e-7f);
    o0.w = c1.w / (c1.z + 1e-7f);
    o1.x = c2.y / (c2.x + 1e-7f);
    o1.y = c2.w / (c2.z + 1e-7f);
    o1.z = c3.y / (c3.x + 1e-7f);
    o1.w = c3.w / (c3.z + 1e-7f);

    float* op = out + (row << 6) + zo;
    *reinterpret_cast<float4*>(op + 0) = o0;
    *reinterpret_cast<float4*>(op + 4) = o1;

    const float4 zf4 = make_float4(0.f, 0.f, 0.f, 0.f);
    *reinterpret_cast<float4*>(rp + 0) = zf4;
    *reinterpret_cast<float4*>(rp + 2) = zf4;
    *reinterpret_cast<float4*>(rp + 4) = zf4;
    *reinterpret_cast<float4*>(rp + 6) = zf4;
}

// ---------------------------------------------------------------------------

extern "C" void kernel_launch(void* const* d_in, const int* in_sizes, int n_in,
                              void* d_out, int out_size) {
    const float* pos  = (const float*)d_in[0];
    const float* prob = (const float*)d_in[1];
    const int*   bidx = (const int*)d_in[2];
    float*       out  = (float*)d_out;

    int L = in_sizes[1];                     // particle count (prob size)

    p2g_scatter_kernel<<<(L + 255) / 256, 256>>>(pos, prob, bidx, L);

    int nocts = out_size / 8;                // B * 4096 rows * 8 octs
    p2g_finalize_kernel<<<(nocts + 255) / 256, 256>>>(out, nocts);
}